// round 1
// baseline (speedup 1.0000x reference)
#include <cuda_runtime.h>
#include <cstdint>

#define BB 128          // batch
#define TT 64           // time steps
#define EE 300          // embed dim
#define HH 2048         // hidden
#define G4 8192         // 4*H

// ---------------- scratch (device globals; no allocation allowed) ----------
__device__ float g_gx[(size_t)TT * BB * G4];   // [T][B][4H] precomputed x-projection + biases (256 MB)
__device__ float g_h[2][BB * HH];              // ping-pong hidden state
__device__ float g_c[BB * HH];                 // cell state

// ---------------- helpers --------------------------------------------------
__device__ __forceinline__ uint32_t smem_u32(const void* p) {
    return (uint32_t)__cvta_generic_to_shared(p);
}
__device__ __forceinline__ void cp16(uint32_t dst, const void* src) {
    asm volatile("cp.async.ca.shared.global [%0], [%1], 16;\n" ::"r"(dst), "l"(src));
}
__device__ __forceinline__ void cp16z(uint32_t dst, const void* src, int bytes) {
    asm volatile("cp.async.ca.shared.global [%0], [%1], 16, %2;\n" ::"r"(dst), "l"(src), "r"(bytes));
}
__device__ __forceinline__ void cp_commit() { asm volatile("cp.async.commit_group;\n"); }
template <int N> __device__ __forceinline__ void cp_wait() {
    asm volatile("cp.async.wait_group %0;\n" ::"n"(N));
}
__device__ __forceinline__ void mma_tf32(float c[4], uint32_t a0, uint32_t a1, uint32_t a2,
                                         uint32_t a3, uint32_t b0, uint32_t b1) {
    asm volatile(
        "mma.sync.aligned.m16n8k8.row.col.f32.tf32.tf32.f32 "
        "{%0,%1,%2,%3},{%4,%5,%6,%7},{%8,%9},{%0,%1,%2,%3};\n"
        : "+f"(c[0]), "+f"(c[1]), "+f"(c[2]), "+f"(c[3])
        : "r"(a0), "r"(a1), "r"(a2), "r"(a3), "r"(b0), "r"(b1));
}
__device__ __forceinline__ float sigmoidf_(float x) { return 1.0f / (1.0f + __expf(-x)); }

// ---------------- tile config ---------------------------------------------
// BM=128 rows, BN=64 cols, BK=32, 256 threads = 8 warps (4 along M x 2 along N).
// Warp tile 32x32 -> per warp 2 (M) x 4 (N) m16n8k8 tiles per k-step.
// Smem: A [2][128][36], B [2][64][36]  (pad 36 floats: 16B-aligned rows + conflict-free frags)
#define LDA 36
#define SMEM_FLOATS (2 * 128 * LDA + 2 * 64 * LDA)
#define SMEM_BYTES (SMEM_FLOATS * 4)

__device__ __forceinline__ void compute_block(const float* __restrict__ As,
                                              const float* __restrict__ Bs,
                                              float acc[2][4][4], int wm, int wn, int g, int tig) {
#pragma unroll
    for (int k8 = 0; k8 < 32; k8 += 8) {
        uint32_t a[2][4];
#pragma unroll
        for (int mt = 0; mt < 2; mt++) {
            int r = wm + mt * 16;
            a[mt][0] = __float_as_uint(As[(r + g) * LDA + k8 + tig]);
            a[mt][1] = __float_as_uint(As[(r + g + 8) * LDA + k8 + tig]);
            a[mt][2] = __float_as_uint(As[(r + g) * LDA + k8 + tig + 4]);
            a[mt][3] = __float_as_uint(As[(r + g + 8) * LDA + k8 + tig + 4]);
        }
        uint32_t b[4][2];
#pragma unroll
        for (int nt = 0; nt < 4; nt++) {
            int cc = wn + nt * 8 + g;
            b[nt][0] = __float_as_uint(Bs[cc * LDA + k8 + tig]);
            b[nt][1] = __float_as_uint(Bs[cc * LDA + k8 + tig + 4]);
        }
#pragma unroll
        for (int mt = 0; mt < 2; mt++)
#pragma unroll
            for (int nt = 0; nt < 4; nt++)
                mma_tf32(acc[mt][nt], a[mt][0], a[mt][1], a[mt][2], a[mt][3], b[nt][0], b[nt][1]);
    }
}

// ---------------- init ------------------------------------------------------
__global__ void zero_kernel() {
    int i = blockIdx.x * blockDim.x + threadIdx.x;
    if (i < BB * HH) {
        g_h[0][i] = 0.f;
        g_c[i] = 0.f;
    }
}

// ---------------- kernel 1: embedding gather + input projection ------------
// gx[t][b][j] = b_ih[j] + b_hh[j] + sum_e embed[input[b][t]][e] * w_ih[j][e]
// grid: (T=64, 128) -> blockIdx.x = t (covers 128 rows b), blockIdx.y*64 = col base
__global__ void __launch_bounds__(256) xproj_kernel(const int* __restrict__ input,
                                                    const float* __restrict__ embed,
                                                    const float* __restrict__ w_ih,
                                                    const float* __restrict__ b_ih,
                                                    const float* __restrict__ b_hh) {
    extern __shared__ float smem[];
    float* As = smem;                    // [2][128][LDA]
    float* Bs = smem + 2 * 128 * LDA;    // [2][64][LDA]
    __shared__ int tok[128];

    const int tid = threadIdx.x;
    const int t = blockIdx.x;
    const int n0 = blockIdx.y * 64;

    if (tid < 128) tok[tid] = input[tid * TT + t];  // input[b][t], b = row
    __syncthreads();

    const int wid = tid >> 5, lane = tid & 31;
    const int wm = (wid & 3) * 32, wn = (wid >> 2) * 32;
    const int g = lane >> 2, tig = lane & 3;

    auto load_tiles = [&](int kb, int s) {
        int k0 = kb * 32;
#pragma unroll
        for (int i = 0; i < 4; i++) {
            int lin = tid + i * 256;
            int row = lin >> 3;
            int kk4 = (lin & 7) * 4;
            int k = k0 + kk4;
            int rem = EE - k;
            int bytes = rem >= 4 ? 16 : (rem > 0 ? rem * 4 : 0);
            const float* src = embed + (size_t)tok[row] * EE + (bytes ? k : 0);
            cp16z(smem_u32(&As[(s * 128 + row) * LDA + kk4]), src, bytes);
        }
#pragma unroll
        for (int i = 0; i < 2; i++) {
            int lin = tid + i * 256;
            int col = lin >> 3;
            int kk4 = (lin & 7) * 4;
            int k = k0 + kk4;
            int rem = EE - k;
            int bytes = rem >= 4 ? 16 : (rem > 0 ? rem * 4 : 0);
            const float* src = w_ih + (size_t)(n0 + col) * EE + (bytes ? k : 0);
            cp16z(smem_u32(&Bs[(s * 64 + col) * LDA + kk4]), src, bytes);
        }
        cp_commit();
    };

    float acc[2][4][4] = {};
    const int NKB = (EE + 31) / 32;  // 10
    load_tiles(0, 0);
    for (int kb = 0; kb < NKB; kb++) {
        if (kb + 1 < NKB) {
            load_tiles(kb + 1, (kb + 1) & 1);
            cp_wait<1>();
        } else {
            cp_wait<0>();
        }
        __syncthreads();
        compute_block(&As[(kb & 1) * 128 * LDA], &Bs[(kb & 1) * 64 * LDA], acc, wm, wn, g, tig);
        __syncthreads();
    }

    // epilogue: add biases, store gx
#pragma unroll
    for (int mt = 0; mt < 2; mt++) {
#pragma unroll
        for (int nt = 0; nt < 4; nt++) {
            int row0 = wm + mt * 16 + g;
            int col0 = wn + nt * 8 + 2 * tig;
            int j0 = n0 + col0;
            float bias0 = b_ih[j0] + b_hh[j0];
            float bias1 = b_ih[j0 + 1] + b_hh[j0 + 1];
            size_t base0 = ((size_t)t * 128 + row0) * G4 + j0;
            g_gx[base0] = acc[mt][nt][0] + bias0;
            g_gx[base0 + 1] = acc[mt][nt][1] + bias1;
            size_t base2 = base0 + (size_t)8 * G4;
            g_gx[base2] = acc[mt][nt][2] + bias0;
            g_gx[base2 + 1] = acc[mt][nt][3] + bias1;
        }
    }
}

// ---------------- kernel 2: one LSTM step (GEMM h@W_hh^T fused with cell) --
// grid: 128 CTAs, CTA handles h-indices [h0, h0+16) for all 4 gates (BN=64 cols).
__global__ void __launch_bounds__(256) step_kernel(int t, const float* __restrict__ w_hh,
                                                   float* __restrict__ d_out) {
    extern __shared__ float smem[];
    float* As = smem;
    float* Bs = smem + 2 * 128 * LDA;

    const float* __restrict__ h_in = g_h[t & 1];
    float* __restrict__ h_out = (t == TT - 1) ? d_out : g_h[(t + 1) & 1];

    const int tid = threadIdx.x;
    const int h0 = blockIdx.x * 16;
    const int wid = tid >> 5, lane = tid & 31;
    const int wm = (wid & 3) * 32, wn = (wid >> 2) * 32;
    const int g = lane >> 2, tig = lane & 3;

    auto load_tiles = [&](int kb, int s) {
        int k0 = kb * 32;
#pragma unroll
        for (int i = 0; i < 4; i++) {
            int lin = tid + i * 256;
            int row = lin >> 3;
            int kk4 = (lin & 7) * 4;
            cp16(smem_u32(&As[(s * 128 + row) * LDA + kk4]), h_in + row * HH + k0 + kk4);
        }
#pragma unroll
        for (int i = 0; i < 2; i++) {
            int lin = tid + i * 256;
            int col = lin >> 3;
            int kk4 = (lin & 7) * 4;
            int gate = col >> 4;
            int j = gate * HH + h0 + (col & 15);
            cp16(smem_u32(&Bs[(s * 64 + col) * LDA + kk4]), w_hh + (size_t)j * HH + k0 + kk4);
        }
        cp_commit();
    };

    float acc[2][4][4] = {};
    const int NKB = HH / 32;  // 64
    load_tiles(0, 0);
    for (int kb = 0; kb < NKB; kb++) {
        if (kb + 1 < NKB) {
            load_tiles(kb + 1, (kb + 1) & 1);
            cp_wait<1>();
        } else {
            cp_wait<0>();
        }
        __syncthreads();
        compute_block(&As[(kb & 1) * 128 * LDA], &Bs[(kb & 1) * 64 * LDA], acc, wm, wn, g, tig);
        __syncthreads();
    }

    // stage gates in smem (reuse As region; 128*65 floats = 33280B <= 36864B)
    float* gsm = smem;
#pragma unroll
    for (int mt = 0; mt < 2; mt++) {
#pragma unroll
        for (int nt = 0; nt < 4; nt++) {
            int row0 = wm + mt * 16 + g;
            int col0 = wn + nt * 8 + 2 * tig;
            gsm[row0 * 65 + col0] = acc[mt][nt][0];
            gsm[row0 * 65 + col0 + 1] = acc[mt][nt][1];
            gsm[(row0 + 8) * 65 + col0] = acc[mt][nt][2];
            gsm[(row0 + 8) * 65 + col0 + 1] = acc[mt][nt][3];
        }
    }
    __syncthreads();

    // LSTM cell update: 128 b x 16 h = 2048 elems, 8 per thread
    const int b = tid >> 1;
    const int hh = (tid & 1) * 8;
    const size_t gxbase = ((size_t)t * BB + b) * G4;
    const int hbase = b * HH + h0 + hh;
#pragma unroll
    for (int i = 0; i < 8; i++) {
        int hc = hh + i;
        float xi = gsm[b * 65 + 0 * 16 + hc] + g_gx[gxbase + 0 * HH + h0 + hc];
        float xf = gsm[b * 65 + 1 * 16 + hc] + g_gx[gxbase + 1 * HH + h0 + hc];
        float xg = gsm[b * 65 + 2 * 16 + hc] + g_gx[gxbase + 2 * HH + h0 + hc];
        float xo = gsm[b * 65 + 3 * 16 + hc] + g_gx[gxbase + 3 * HH + h0 + hc];
        float ig = sigmoidf_(xi);
        float fg = sigmoidf_(xf);
        float gg = tanhf(xg);
        float og = sigmoidf_(xo);
        float cn = fg * g_c[hbase + i] + ig * gg;
        g_c[hbase + i] = cn;
        h_out[hbase + i] = og * tanhf(cn);
    }
}

// ---------------- launch ----------------------------------------------------
extern "C" void kernel_launch(void* const* d_in, const int* in_sizes, int n_in, void* d_out,
                              int out_size) {
    const int* input = (const int*)d_in[0];
    const float* embed = (const float*)d_in[1];
    const float* w_ih = (const float*)d_in[2];
    const float* w_hh = (const float*)d_in[3];
    const float* b_ih = (const float*)d_in[4];
    const float* b_hh = (const float*)d_in[5];
    float* out = (float*)d_out;

    cudaFuncSetAttribute(xproj_kernel, cudaFuncAttributeMaxDynamicSharedMemorySize, SMEM_BYTES);
    cudaFuncSetAttribute(step_kernel, cudaFuncAttributeMaxDynamicSharedMemorySize, SMEM_BYTES);

    zero_kernel<<<(BB * HH + 255) / 256, 256>>>();
    xproj_kernel<<<dim3(TT, 128), 256, SMEM_BYTES>>>(input, embed, w_ih, b_ih, b_hh);
    for (int t = 0; t < TT; t++) {
        step_kernel<<<128, 256, SMEM_BYTES>>>(t, w_hh, out);
    }
}

// round 2
// speedup vs baseline: 1.0245x; 1.0245x over previous
#include <cuda_runtime.h>
#include <cstdint>

#define BB 128          // batch
#define TT 64           // time steps
#define EE 300          // embed dim
#define HH 2048         // hidden
#define G4 8192         // 4*H

// ---------------- scratch (device globals; no allocation allowed) ----------
__device__ float g_gx[(size_t)TT * BB * G4];   // [T][B][4H] precomputed x-projection + biases
__device__ float g_h[2][BB * HH];              // ping-pong hidden state
__device__ float g_c[BB * HH];                 // cell state

// ---------------- helpers --------------------------------------------------
__device__ __forceinline__ uint32_t smem_u32(const void* p) {
    return (uint32_t)__cvta_generic_to_shared(p);
}
__device__ __forceinline__ void cp16(uint32_t dst, const void* src) {
    asm volatile("cp.async.ca.shared.global [%0], [%1], 16;\n" ::"r"(dst), "l"(src));
}
__device__ __forceinline__ void cp16z(uint32_t dst, const void* src, int bytes) {
    asm volatile("cp.async.ca.shared.global [%0], [%1], 16, %2;\n" ::"r"(dst), "l"(src), "r"(bytes));
}
__device__ __forceinline__ void cp_commit() { asm volatile("cp.async.commit_group;\n"); }
template <int N> __device__ __forceinline__ void cp_wait() {
    asm volatile("cp.async.wait_group %0;\n" ::"n"(N));
}
__device__ __forceinline__ void mma_tf32(float c[4], uint32_t a0, uint32_t a1, uint32_t a2,
                                         uint32_t a3, uint32_t b0, uint32_t b1) {
    asm volatile(
        "mma.sync.aligned.m16n8k8.row.col.f32.tf32.tf32.f32 "
        "{%0,%1,%2,%3},{%4,%5,%6,%7},{%8,%9},{%0,%1,%2,%3};\n"
        : "+f"(c[0]), "+f"(c[1]), "+f"(c[2]), "+f"(c[3])
        : "r"(a0), "r"(a1), "r"(a2), "r"(a3), "r"(b0), "r"(b1));
}
__device__ __forceinline__ float sigmoidf_(float x) { return 1.0f / (1.0f + __expf(-x)); }

// ---------------- tile config ---------------------------------------------
// BM=128 rows, BN=64 cols, BK=32, 256 threads = 8 warps (4 along M x 2 along N).
// Warp tile 32x32 -> per warp 2 (M) x 4 (N) m16n8k8 tiles per k-step.
#define LDA 36
#define STAGE_FLOATS ((128 + 64) * LDA)           // A tile then B tile, per stage
#define NSTAGE 5
#define STEP_SMEM_BYTES (NSTAGE * STAGE_FLOATS * 4)   // 138240 B
#define XP_SMEM_BYTES (2 * STAGE_FLOATS * 4)

__device__ __forceinline__ void compute_block(const float* __restrict__ As,
                                              const float* __restrict__ Bs,
                                              float acc[2][4][4], int wm, int wn, int g, int tig) {
#pragma unroll
    for (int k8 = 0; k8 < 32; k8 += 8) {
        uint32_t a[2][4];
#pragma unroll
        for (int mt = 0; mt < 2; mt++) {
            int r = wm + mt * 16;
            a[mt][0] = __float_as_uint(As[(r + g) * LDA + k8 + tig]);
            a[mt][1] = __float_as_uint(As[(r + g + 8) * LDA + k8 + tig]);
            a[mt][2] = __float_as_uint(As[(r + g) * LDA + k8 + tig + 4]);
            a[mt][3] = __float_as_uint(As[(r + g + 8) * LDA + k8 + tig + 4]);
        }
        uint32_t b[4][2];
#pragma unroll
        for (int nt = 0; nt < 4; nt++) {
            int cc = wn + nt * 8 + g;
            b[nt][0] = __float_as_uint(Bs[cc * LDA + k8 + tig]);
            b[nt][1] = __float_as_uint(Bs[cc * LDA + k8 + tig + 4]);
        }
#pragma unroll
        for (int mt = 0; mt < 2; mt++)
#pragma unroll
            for (int nt = 0; nt < 4; nt++)
                mma_tf32(acc[mt][nt], a[mt][0], a[mt][1], a[mt][2], a[mt][3], b[nt][0], b[nt][1]);
    }
}

// ---------------- init ------------------------------------------------------
__global__ void zero_kernel() {
    int i = blockIdx.x * blockDim.x + threadIdx.x;
    if (i < BB * HH) {
        g_h[0][i] = 0.f;
        g_c[i] = 0.f;
    }
}

// ---------------- kernel 1: embedding gather + input projection ------------
// gx[t][b][j] = b_ih[j] + b_hh[j] + sum_e embed[input[b][t]][e] * w_ih[j][e]
__global__ void __launch_bounds__(256) xproj_kernel(const int* __restrict__ input,
                                                    const float* __restrict__ embed,
                                                    const float* __restrict__ w_ih,
                                                    const float* __restrict__ b_ih,
                                                    const float* __restrict__ b_hh) {
    extern __shared__ float smem[];
    __shared__ int tok[128];

    const int tid = threadIdx.x;
    const int t = blockIdx.x;
    const int n0 = blockIdx.y * 64;

    if (tid < 128) tok[tid] = input[tid * TT + t];  // input[b][t], b = row
    __syncthreads();

    const int wid = tid >> 5, lane = tid & 31;
    const int wm = (wid & 3) * 32, wn = (wid >> 2) * 32;
    const int g = lane >> 2, tig = lane & 3;

    auto load_tiles = [&](int kb, int s) {
        float* As = smem + s * STAGE_FLOATS;
        float* Bs = As + 128 * LDA;
        int k0 = kb * 32;
#pragma unroll
        for (int i = 0; i < 4; i++) {
            int lin = tid + i * 256;
            int row = lin >> 3;
            int kk4 = (lin & 7) * 4;
            int k = k0 + kk4;
            int rem = EE - k;
            int bytes = rem >= 4 ? 16 : (rem > 0 ? rem * 4 : 0);
            const float* src = embed + (size_t)tok[row] * EE + (bytes ? k : 0);
            cp16z(smem_u32(&As[row * LDA + kk4]), src, bytes);
        }
#pragma unroll
        for (int i = 0; i < 2; i++) {
            int lin = tid + i * 256;
            int col = lin >> 3;
            int kk4 = (lin & 7) * 4;
            int k = k0 + kk4;
            int rem = EE - k;
            int bytes = rem >= 4 ? 16 : (rem > 0 ? rem * 4 : 0);
            const float* src = w_ih + (size_t)(n0 + col) * EE + (bytes ? k : 0);
            cp16z(smem_u32(&Bs[col * LDA + kk4]), src, bytes);
        }
        cp_commit();
    };

    float acc[2][4][4] = {};
    const int NKB = (EE + 31) / 32;  // 10
    load_tiles(0, 0);
    for (int kb = 0; kb < NKB; kb++) {
        if (kb + 1 < NKB) {
            load_tiles(kb + 1, (kb + 1) & 1);
            cp_wait<1>();
        } else {
            cp_wait<0>();
        }
        __syncthreads();
        const float* As = smem + (kb & 1) * STAGE_FLOATS;
        compute_block(As, As + 128 * LDA, acc, wm, wn, g, tig);
        __syncthreads();
    }

    // epilogue: add biases, store gx
#pragma unroll
    for (int mt = 0; mt < 2; mt++) {
#pragma unroll
        for (int nt = 0; nt < 4; nt++) {
            int row0 = wm + mt * 16 + g;
            int col0 = wn + nt * 8 + 2 * tig;
            int j0 = n0 + col0;
            float bias0 = b_ih[j0] + b_hh[j0];
            float bias1 = b_ih[j0 + 1] + b_hh[j0 + 1];
            size_t base0 = ((size_t)t * 128 + row0) * G4 + j0;
            g_gx[base0] = acc[mt][nt][0] + bias0;
            g_gx[base0 + 1] = acc[mt][nt][1] + bias1;
            size_t base2 = base0 + (size_t)8 * G4;
            g_gx[base2] = acc[mt][nt][2] + bias0;
            g_gx[base2 + 1] = acc[mt][nt][3] + bias1;
        }
    }
}

// ---------------- kernel 2: one LSTM step (GEMM h@W_hh^T fused with cell) --
// grid: 128 CTAs, CTA handles h-indices [h0, h0+16) for all 4 gates (BN=64 cols).
// 5-stage cp.async pipeline, ONE barrier per k-iteration.
__global__ void __launch_bounds__(256) step_kernel(int t, const float* __restrict__ w_hh,
                                                   float* __restrict__ d_out) {
    extern __shared__ float smem[];

    const float* __restrict__ h_in = g_h[t & 1];
    float* __restrict__ h_out = (t == TT - 1) ? d_out : g_h[(t + 1) & 1];

    const int tid = threadIdx.x;
    const int h0 = blockIdx.x * 16;
    const int wid = tid >> 5, lane = tid & 31;
    const int wm = (wid & 3) * 32, wn = (wid >> 2) * 32;
    const int g = lane >> 2, tig = lane & 3;

    // per-thread precomputed load coordinates
    auto issue_stage = [&](int kb, int s) {
        float* As = smem + s * STAGE_FLOATS;
        float* Bs = As + 128 * LDA;
        int k0 = kb * 32;
#pragma unroll
        for (int i = 0; i < 4; i++) {
            int lin = tid + i * 256;
            int row = lin >> 3;
            int kk4 = (lin & 7) * 4;
            cp16(smem_u32(&As[row * LDA + kk4]), h_in + row * HH + k0 + kk4);
        }
#pragma unroll
        for (int i = 0; i < 2; i++) {
            int lin = tid + i * 256;
            int col = lin >> 3;
            int kk4 = (lin & 7) * 4;
            int gate = col >> 4;
            int j = gate * HH + h0 + (col & 15);
            cp16(smem_u32(&Bs[col * LDA + kk4]), w_hh + (size_t)j * HH + k0 + kk4);
        }
    };

    float acc[2][4][4] = {};
    const int NKB = HH / 32;  // 64

    // prefetch NSTAGE-1 stages
#pragma unroll
    for (int p = 0; p < NSTAGE - 1; p++) {
        issue_stage(p, p);
        cp_commit();
    }

    int s = 0;
    for (int kb = 0; kb < NKB; kb++) {
        cp_wait<NSTAGE - 2>();   // stage kb's group is complete
        __syncthreads();         // visibility + frees stage (kb-1)%NSTAGE for rewrite
        int kn = kb + NSTAGE - 1;
        if (kn < NKB) issue_stage(kn, kn % NSTAGE);
        cp_commit();             // always commit (empty groups keep the count exact in tail)
        const float* As = smem + s * STAGE_FLOATS;
        compute_block(As, As + 128 * LDA, acc, wm, wn, g, tig);
        s = (s + 1 == NSTAGE) ? 0 : s + 1;
    }

    // ensure every warp is done computing before overwriting stages 0/1 with gates
    __syncthreads();

    // stage gates in smem (reuse stage 0/1 region; 128*65 floats = 33280B)
    float* gsm = smem;
#pragma unroll
    for (int mt = 0; mt < 2; mt++) {
#pragma unroll
        for (int nt = 0; nt < 4; nt++) {
            int row0 = wm + mt * 16 + g;
            int col0 = wn + nt * 8 + 2 * tig;
            gsm[row0 * 65 + col0] = acc[mt][nt][0];
            gsm[row0 * 65 + col0 + 1] = acc[mt][nt][1];
            gsm[(row0 + 8) * 65 + col0] = acc[mt][nt][2];
            gsm[(row0 + 8) * 65 + col0 + 1] = acc[mt][nt][3];
        }
    }
    __syncthreads();

    // LSTM cell update: 128 b x 16 h = 2048 elems, 8 per thread
    const int b = tid >> 1;
    const int hh = (tid & 1) * 8;
    const size_t gxbase = ((size_t)t * BB + b) * G4;
    const int hbase = b * HH + h0 + hh;
#pragma unroll
    for (int i = 0; i < 8; i++) {
        int hc = hh + i;
        float xi = gsm[b * 65 + 0 * 16 + hc] + g_gx[gxbase + 0 * HH + h0 + hc];
        float xf = gsm[b * 65 + 1 * 16 + hc] + g_gx[gxbase + 1 * HH + h0 + hc];
        float xg = gsm[b * 65 + 2 * 16 + hc] + g_gx[gxbase + 2 * HH + h0 + hc];
        float xo = gsm[b * 65 + 3 * 16 + hc] + g_gx[gxbase + 3 * HH + h0 + hc];
        float ig = sigmoidf_(xi);
        float fg = sigmoidf_(xf);
        float gg = tanhf(xg);
        float og = sigmoidf_(xo);
        float cn = fg * g_c[hbase + i] + ig * gg;
        g_c[hbase + i] = cn;
        h_out[hbase + i] = og * tanhf(cn);
    }
}

// ---------------- launch ----------------------------------------------------
extern "C" void kernel_launch(void* const* d_in, const int* in_sizes, int n_in, void* d_out,
                              int out_size) {
    const int* input = (const int*)d_in[0];
    const float* embed = (const float*)d_in[1];
    const float* w_ih = (const float*)d_in[2];
    const float* w_hh = (const float*)d_in[3];
    const float* b_ih = (const float*)d_in[4];
    const float* b_hh = (const float*)d_in[5];
    float* out = (float*)d_out;

    cudaFuncSetAttribute(xproj_kernel, cudaFuncAttributeMaxDynamicSharedMemorySize, XP_SMEM_BYTES);
    cudaFuncSetAttribute(step_kernel, cudaFuncAttributeMaxDynamicSharedMemorySize, STEP_SMEM_BYTES);

    zero_kernel<<<(BB * HH + 255) / 256, 256>>>();
    xproj_kernel<<<dim3(TT, 128), 256, XP_SMEM_BYTES>>>(input, embed, w_ih, b_ih, b_hh);
    for (int t = 0; t < TT; t++) {
        step_kernel<<<128, 256, STEP_SMEM_BYTES>>>(t, w_hh, out);
    }
}